// round 17
// baseline (speedup 1.0000x reference)
#include <cuda_runtime.h>
#include <cuda_fp16.h>
#include <math.h>
#include <stdint.h>

// Problem constants
#define DD   1024
#define HH   2048
#define EE   8
#define TT   8192
#define KTOP 2
#define NMOE (TT * KTOP)
#define NROWS (NMOE + TT)

#define XSZ   ((size_t)TT * DD)
#define WSZ   ((size_t)EE * DD * HH)
#define SWSZ  ((size_t)DD * HH)

// ---------------------------------------------------------------------------
// Scratch (static __device__ globals)
// ---------------------------------------------------------------------------
__device__ __half g_hidden[(size_t)NROWS * HH];   // fp16 activations
__device__ __half g_xh[XSZ];                      // x fp16, [T][D] (written by prep)
__device__ __half g_w1h[WSZ];                     // W1^T fp16: [E][H][D]
__device__ __half g_w3h[WSZ];
__device__ __half g_w2h[WSZ];                     // W2^T fp16: [E][D][H]
__device__ __half g_sw1h[SWSZ];
__device__ __half g_sw3h[SWSZ];
__device__ __half g_sw2h[SWSZ];
__device__ int   g_count[EE];
__device__ int   g_tok[EE * TT];                  // per-expert token lists
__device__ float g_wt[EE * TT];                   // per-expert combine weights (by pos)

// ---------------------------------------------------------------------------
// Helpers
// ---------------------------------------------------------------------------
__device__ __forceinline__ void mma16(float c[4], const uint32_t a[4], const uint32_t* b) {
    asm volatile(
        "mma.sync.aligned.m16n8k16.row.col.f32.f16.f16.f32 "
        "{%0,%1,%2,%3},{%4,%5,%6,%7},{%8,%9},{%0,%1,%2,%3};\n"
        : "+f"(c[0]), "+f"(c[1]), "+f"(c[2]), "+f"(c[3])
        : "r"(a[0]), "r"(a[1]), "r"(a[2]), "r"(a[3]), "r"(b[0]), "r"(b[1]));
}

__device__ __forceinline__ void ldsm4(uint32_t r[4], uint32_t addr) {
    asm volatile("ldmatrix.sync.aligned.m8n8.x4.shared.b16 {%0,%1,%2,%3}, [%4];"
                 : "=r"(r[0]), "=r"(r[1]), "=r"(r[2]), "=r"(r[3]) : "r"(addr));
}

// L2-only (bypass L1): GEMM operands have zero intra-CTA reuse.
__device__ __forceinline__ void cp16(uint32_t smem_dst, const void* gmem_src, int src_size) {
    asm volatile("cp.async.cg.shared.global [%0], [%1], 16, %2;"
                 :: "r"(smem_dst), "l"(gmem_src), "r"(src_size));
}
__device__ __forceinline__ void cp_commit() { asm volatile("cp.async.commit_group;"); }
__device__ __forceinline__ void cp_wait2()  { asm volatile("cp.async.wait_group 2;" ::: "memory"); }

__device__ __forceinline__ void red2(float* ptr, float v0, float v1) {
    asm volatile("red.global.add.v2.f32 [%0], {%1, %2};"
                 :: "l"(ptr), "f"(v0), "f"(v1) : "memory");
}

__device__ __forceinline__ float silu_f(float v) { return v / (1.0f + __expf(-v)); }

// per-CTA prefix over g_count: rowbase of group g (g == EE -> NMOE)
__device__ __forceinline__ void group_range(int g, int& M, int& rowbase) {
    if (g >= EE) { M = TT; rowbase = NMOE; return; }
    int rb = 0;
#pragma unroll
    for (int e = 0; e < EE; e++) {
        int c = g_count[e];
        if (e < g) rb += c;
        if (e == g) M = c;
    }
    rowbase = rb;
}

// shared transpose helper: [K][N] src tile (k0,n0) -> [N][K] dst, fp16
__device__ __forceinline__ void trans_tile(const float* __restrict__ src,
                                           __half* __restrict__ dst,
                                           int K, int N, int n0, int k0) {
    __shared__ float t[32][33];
    int tx = threadIdx.x & 31, ty = threadIdx.x >> 5;
#pragma unroll
    for (int i = 0; i < 4; i++)
        t[ty + 8 * i][tx] = src[(size_t)(k0 + ty + 8 * i) * N + n0 + tx];
    __syncthreads();
#pragma unroll
    for (int i = 0; i < 4; i++)
        dst[(size_t)(n0 + ty + 8 * i) * K + k0 + tx] = __float2half_rn(t[tx][ty + 8 * i]);
}

// ---------------------------------------------------------------------------
// PREP (fused): router (+x->fp16) | out-zero + counter reset | w1/w3/sw1/sw3 transpose
// flat grid: [0,1024) router, [1024,9216) zero, [9216,46080) f1 transposes
// ---------------------------------------------------------------------------
#define PREP_ROUTER 1024
#define PREP_ZERO   (PREP_ROUTER + 8192)
#define PREP_F1     (PREP_ZERO + 36864)

__global__ void prep_kernel(const float* __restrict__ x, const float* __restrict__ rw,
                            const float* __restrict__ bias,
                            const float* __restrict__ w1, const float* __restrict__ w3,
                            const float* __restrict__ sw1, const float* __restrict__ sw3,
                            __half* __restrict__ d1, __half* __restrict__ d3,
                            __half* __restrict__ ds1, __half* __restrict__ ds3,
                            float4* __restrict__ out) {
    int bid = blockIdx.x;

    if (bid < PREP_ROUTER) {
        // ---- router: one warp per token, fused x->fp16 emit ----
        int warp = threadIdx.x >> 5;
        int lane = threadIdx.x & 31;
        int t = bid * 8 + warp;

        const float4* xr4 = reinterpret_cast<const float4*>(x + (size_t)t * DD);
        float4 xv[8];
#pragma unroll
        for (int i = 0; i < 8; i++) xv[i] = xr4[lane + (i << 5)];

        uint2* xh4 = reinterpret_cast<uint2*>(g_xh + (size_t)t * DD);
#pragma unroll
        for (int i = 0; i < 8; i++) {
            __half2 h0 = __floats2half2_rn(xv[i].x, xv[i].y);
            __half2 h1 = __floats2half2_rn(xv[i].z, xv[i].w);
            uint2 o;
            o.x = *reinterpret_cast<uint32_t*>(&h0);
            o.y = *reinterpret_cast<uint32_t*>(&h1);
            xh4[lane + (i << 5)] = o;
        }

        float logit[EE];
#pragma unroll
        for (int e = 0; e < EE; e++) {
            const float4* we4 = reinterpret_cast<const float4*>(rw + (size_t)e * DD);
            float acc = 0.0f;
#pragma unroll
            for (int i = 0; i < 8; i++) {
                float4 w4 = we4[lane + (i << 5)];
                acc += xv[i].x * w4.x + xv[i].y * w4.y + xv[i].z * w4.z + xv[i].w * w4.w;
            }
#pragma unroll
            for (int o = 16; o > 0; o >>= 1) acc += __shfl_xor_sync(0xffffffffu, acc, o);
            logit[e] = acc + bias[e];
        }

        if (lane == 0) {
            int e0 = 0;
#pragma unroll
            for (int e = 1; e < EE; e++) if (logit[e] > logit[e0]) e0 = e;
            int e1 = -1;
#pragma unroll
            for (int e = 0; e < EE; e++) {
                if (e == e0) continue;
                if (e1 < 0 || logit[e] > logit[e1]) e1 = e;
            }
            float l0 = logit[e0], l1 = logit[e1];
            float p1 = expf(l1 - l0);
            float inv = 1.0f / (1.0f + p1);

            int pos0 = atomicAdd(&g_count[e0], 1);
            int pos1 = atomicAdd(&g_count[e1], 1);
            g_tok[e0 * TT + pos0] = t;
            g_tok[e1 * TT + pos1] = t;
            g_wt[e0 * TT + pos0] = inv;
            g_wt[e1 * TT + pos1] = p1 * inv;
        }
    } else if (bid < PREP_ZERO) {
        // ---- zero out ----
        int i = (bid - PREP_ROUTER) * 256 + threadIdx.x;
        out[i] = make_float4(0.f, 0.f, 0.f, 0.f);
    } else {
        // ---- w1/w3/sw1/sw3 transpose+convert: [D][H] -> [H][D] ----
        int idx = bid - PREP_ZERO;                 // 0..36863
        int xb = idx & 63;                         // HH/32 = 64
        int yb = (idx >> 6) & 31;                  // DD/32 = 32
        int z  = idx >> 11;                        // 0..17
        const float* src;
        __half* dst;
        if (z < EE)            { src = w1  + (size_t)z * DD * HH;        dst = d1  + (size_t)z * DD * HH; }
        else if (z < 2 * EE)   { src = w3  + (size_t)(z - EE) * DD * HH; dst = d3  + (size_t)(z - EE) * DD * HH; }
        else if (z == 2 * EE)  { src = sw1;                              dst = ds1; }
        else                   { src = sw3;                              dst = ds3; }
        trans_tile(src, dst, DD, HH, xb * 32, yb * 32);
    }
}

// NOTE: the counter reset must happen before the router atomics. The router
// blocks and the reset cannot be in the same kernel without ordering. Reset is
// done host-side impossible (no memset in capture?) -- cudaMemsetAsync IS
// capturable. We use a tiny reset kernel prepended instead (safe, ~3us).
__global__ void reset_counts_kernel() {
    if (threadIdx.x < EE) g_count[threadIdx.x] = 0;
}

// ---------------------------------------------------------------------------
// GEMM1 (dual fp16) fused with w2/sw2 transpose.
// flat grid: [0,18432) gemm 128x64(dual) tiles, [18432,36864) w2 transposes
// ---------------------------------------------------------------------------
#define A_OFF    0
#define A_WORDS  (128 * 20)
#define B1_OFF   A_WORDS
#define B1_WORDS (64 * 20)
#define B3_OFF   (B1_OFF + B1_WORDS)
#define STG1_WORDS (A_WORDS + 2 * B1_WORDS)
#define STG1_BYTES (STG1_WORDS * 4)
#define SMEM1_BYTES (4 * STG1_BYTES)        // 81920
#define G1_BLOCKS (64 * 32 * 9)             // 18432

__global__ __launch_bounds__(256, 2)
void gemm1_kernel(const float* __restrict__ w2, const float* __restrict__ sw2,
                  __half* __restrict__ d2, __half* __restrict__ ds2) {
    extern __shared__ uint32_t smemw[];

    int bid = blockIdx.x;
    if (bid >= G1_BLOCKS) {
        // ---- w2/sw2 transpose+convert: [H][D] -> [D][H] ----
        int idx = bid - G1_BLOCKS;                 // 0..18431
        int xb = idx & 31;                         // DD/32 = 32
        int yb = (idx >> 5) & 63;                  // HH/32 = 64
        int z  = idx >> 11;                        // 0..8
        const float* src = (z < EE) ? (w2 + (size_t)z * HH * DD) : sw2;
        __half* dst      = (z < EE) ? (d2 + (size_t)z * HH * DD) : ds2;
        trans_tile(src, dst, HH, DD, xb * 32, yb * 32);
        return;
    }

    int bx = bid & 63, by = (bid >> 6) & 31, g = bid >> 11;
    int M, rowbase;
    group_range(g, M, rowbase);
    const int* toks = (g < EE) ? (g_tok + g * TT) : nullptr;
    const __half *W1H, *W3H;
    if (g < EE) {
        W1H = g_w1h + (size_t)g * DD * HH; W3H = g_w3h + (size_t)g * DD * HH;
    } else {
        W1H = g_sw1h; W3H = g_sw3h;
    }
    int bm0 = bx * 128;
    if (bm0 >= M) return;
    int n0 = by * 64;

    int tid  = threadIdx.x;
    int lane = tid & 31, wid = tid >> 5;
    int wm = wid & 3, wn = wid >> 2;       // 4x2 warps -> 32x32 per warp (dual)
    int t4 = lane & 3, t8 = lane >> 2;

    float accG[2][4][4] = {}, accU[2][4][4] = {};

    // producer: 1024 chunks (A 512, B1 256, B3 256) -> 4 per thread
    const __half* src[4];
    int sz[4], off[4];
#pragma unroll
    for (int j = 0; j < 4; j++) {
        int c = tid + 256 * j;
        if (c < 512) {
            int row = c >> 2, kw = (c & 3) << 2;
            int gm = bm0 + row;
            if (gm < M) {
                int tr = toks ? toks[gm] : gm;
                src[j] = g_xh + (size_t)tr * DD + kw * 2; sz[j] = 16;
            } else { src[j] = g_xh; sz[j] = 0; }
            off[j] = A_OFF + row * 20 + kw;
        } else if (c < 768) {
            int n = (c - 512) >> 2, kw = (c & 3) << 2;
            src[j] = W1H + (size_t)(n0 + n) * DD + kw * 2; sz[j] = 16;
            off[j] = B1_OFF + n * 20 + kw;
        } else {
            int n = (c - 768) >> 2, kw = (c & 3) << 2;
            src[j] = W3H + (size_t)(n0 + n) * DD + kw * 2; sz[j] = 16;
            off[j] = B3_OFF + n * 20 + kw;
        }
    }

    uint32_t sbase = (uint32_t)__cvta_generic_to_shared(smemw);

    int awo[2];
#pragma unroll
    for (int mi = 0; mi < 2; mi++)
        awo[mi] = A_OFF + (wm * 32 + mi * 16 + (lane & 15)) * 20 + ((lane >> 4) << 2);
    int bwo1[2], bwo3[2];
#pragma unroll
    for (int p = 0; p < 2; p++) {
        int rowoff = (wn * 32 + p * 16 + ((lane >> 4) << 3) + (lane & 7)) * 20
                   + (((lane >> 3) & 1) << 2);
        bwo1[p] = B1_OFF + rowoff;
        bwo3[p] = B3_OFF + rowoff;
    }

#pragma unroll
    for (int p = 0; p < 2; p++) {
        uint32_t sb = sbase + p * STG1_BYTES;
        int k0 = p * 32;
#pragma unroll
        for (int j = 0; j < 4; j++) cp16(sb + off[j] * 4, src[j] + k0, sz[j]);
        cp_commit();
    }

    const int KB = DD / 32;
    for (int kb = 0; kb < KB; kb++) {
        if (kb + 2 < KB) {
            uint32_t sb = sbase + ((kb + 2) & 3) * STG1_BYTES;
            int k0 = (kb + 2) * 32;
#pragma unroll
            for (int j = 0; j < 4; j++) cp16(sb + off[j] * 4, src[j] + k0, sz[j]);
        }
        cp_commit();
        cp_wait2();
        __syncthreads();

        uint32_t stgb = sbase + (kb & 3) * STG1_BYTES;

#pragma unroll
        for (int ks = 0; ks < 2; ks++) {
            uint32_t kofs = stgb + ks * 32;
            uint32_t a[2][4], b1[2][4], b3[2][4];
            ldsm4(a[0],  kofs + awo[0] * 4);
            ldsm4(a[1],  kofs + awo[1] * 4);
            ldsm4(b1[0], kofs + bwo1[0] * 4);
            ldsm4(b1[1], kofs + bwo1[1] * 4);
            ldsm4(b3[0], kofs + bwo3[0] * 4);
            ldsm4(b3[1], kofs + bwo3[1] * 4);
#pragma unroll
            for (int mi = 0; mi < 2; mi++)
#pragma unroll
                for (int nj = 0; nj < 4; nj++) {
                    mma16(accG[mi][nj], a[mi], &b1[nj >> 1][(nj & 1) * 2]);
                    mma16(accU[mi][nj], a[mi], &b3[nj >> 1][(nj & 1) * 2]);
                }
        }
    }

    // epilogue: silu(G)*U -> g_hidden (fp16)
#pragma unroll
    for (int mi = 0; mi < 2; mi++) {
#pragma unroll
        for (int h = 0; h < 2; h++) {
            int row = wm * 32 + mi * 16 + t8 + h * 8;
            int grow = bm0 + row;
            if (grow < M) {
                size_t base = (size_t)(rowbase + grow) * HH + n0;
#pragma unroll
                for (int nj = 0; nj < 4; nj++) {
                    int col = wn * 32 + nj * 8 + t4 * 2;
                    float v0 = silu_f(accG[mi][nj][h * 2 + 0]) * accU[mi][nj][h * 2 + 0];
                    float v1 = silu_f(accG[mi][nj][h * 2 + 1]) * accU[mi][nj][h * 2 + 1];
                    __half2 hh = __floats2half2_rn(v0, v1);
                    *reinterpret_cast<__half2*>(&g_hidden[base + col]) = hh;
                }
            }
        }
    }
}

// ---------------------------------------------------------------------------
// GEMM2 (fp16): out += w * (hidden @ W2). CTA 128x128, warp 32x64, K32 stages,
// ldmatrix, fused weighted reduction epilogue.
// ---------------------------------------------------------------------------
#define B2_OFF   A_WORDS
#define B2_WORDS (128 * 20)
#define STG2_WORDS (A_WORDS + B2_WORDS)
#define STG2_BYTES (STG2_WORDS * 4)
#define SMEM2_BYTES (4 * STG2_BYTES)        // 81920

__global__ __launch_bounds__(256, 2)
void gemm2_kernel(float* __restrict__ out) {
    extern __shared__ uint32_t smemw[];

    int g = blockIdx.z;
    int M, rowbase;
    group_range(g, M, rowbase);
    const int* toks  = (g < EE) ? (g_tok + g * TT) : nullptr;
    const float* wts = (g < EE) ? (g_wt + g * TT) : nullptr;
    const __half* W2H = (g < EE) ? (g_w2h + (size_t)g * HH * DD) : g_sw2h;

    int bm0 = blockIdx.x * 128;
    if (bm0 >= M) return;
    int n0 = blockIdx.y * 128;

    int tid  = threadIdx.x;
    int lane = tid & 31, wid = tid >> 5;
    int wm = wid & 3, wn = wid >> 2;       // warp 32 x 64
    int t4 = lane & 3, t8 = lane >> 2;

    float acc[2][8][4] = {};

    const __half* src[4];
    int sz[4], off[4];
#pragma unroll
    for (int j = 0; j < 4; j++) {
        int c = tid + 256 * j;
        if (c < 512) {
            int row = c >> 2, kw = (c & 3) << 2;
            int gm = bm0 + row;
            if (gm < M) {
                src[j] = g_hidden + (size_t)(rowbase + gm) * HH + kw * 2; sz[j] = 16;
            } else { src[j] = g_hidden; sz[j] = 0; }
            off[j] = A_OFF + row * 20 + kw;
        } else {
            int n = (c - 512) >> 2, kw = (c & 3) << 2;
            src[j] = W2H + (size_t)(n0 + n) * HH + kw * 2; sz[j] = 16;
            off[j] = B2_OFF + n * 20 + kw;
        }
    }

    uint32_t sbase = (uint32_t)__cvta_generic_to_shared(smemw);

    int awo[2];
#pragma unroll
    for (int mi = 0; mi < 2; mi++)
        awo[mi] = A_OFF + (wm * 32 + mi * 16 + (lane & 15)) * 20 + ((lane >> 4) << 2);
    int bwo[4];
#pragma unroll
    for (int p = 0; p < 4; p++) {
        bwo[p] = B2_OFF + (wn * 64 + p * 16 + ((lane >> 4) << 3) + (lane & 7)) * 20
               + (((lane >> 3) & 1) << 2);
    }

#pragma unroll
    for (int p = 0; p < 2; p++) {
        uint32_t sb = sbase + p * STG2_BYTES;
        int k0 = p * 32;
#pragma unroll
        for (int j = 0; j < 4; j++) cp16(sb + off[j] * 4, src[j] + k0, sz[j]);
        cp_commit();
    }

    const int KB = HH / 32;
    for (int kb = 0; kb < KB; kb++) {
        if (kb + 2 < KB) {
            uint32_t sb = sbase + ((kb + 2) & 3) * STG2_BYTES;
            int k0 = (kb + 2) * 32;
#pragma unroll
            for (int j = 0; j < 4; j++) cp16(sb + off[j] * 4, src[j] + k0, sz[j]);
        }
        cp_commit();
        cp_wait2();
        __syncthreads();

        uint32_t stgb = sbase + (kb & 3) * STG2_BYTES;

#pragma unroll
        for (int ks = 0; ks < 2; ks++) {
            uint32_t kofs = stgb + ks * 32;
            uint32_t a[2][4], bb[4][4];
            ldsm4(a[0], kofs + awo[0] * 4);
            ldsm4(a[1], kofs + awo[1] * 4);
#pragma unroll
            for (int p = 0; p < 4; p++) ldsm4(bb[p], kofs + bwo[p] * 4);
#pragma unroll
            for (int mi = 0; mi < 2; mi++)
#pragma unroll
                for (int nj = 0; nj < 8; nj++)
                    mma16(acc[mi][nj], a[mi], &bb[nj >> 1][(nj & 1) * 2]);
        }
    }

    // epilogue: weighted atomic reduction into out
#pragma unroll
    for (int mi = 0; mi < 2; mi++) {
#pragma unroll
        for (int h = 0; h < 2; h++) {
            int row = wm * 32 + mi * 16 + t8 + h * 8;
            int grow = bm0 + row;
            if (grow < M) {
                int tok;
                float w;
                if (g < EE) { tok = toks[grow]; w = wts[grow]; }
                else        { tok = grow;       w = 1.0f; }
                float* obase = out + (size_t)tok * DD + n0;
#pragma unroll
                for (int nj = 0; nj < 8; nj++) {
                    int col = wn * 64 + nj * 8 + t4 * 2;
                    red2(obase + col,
                         w * acc[mi][nj][h * 2 + 0],
                         w * acc[mi][nj][h * 2 + 1]);
                }
            }
        }
    }
}

// ---------------------------------------------------------------------------
// Launch
// ---------------------------------------------------------------------------
extern "C" void kernel_launch(void* const* d_in, const int* in_sizes, int n_in,
                              void* d_out, int out_size) {
    const float* x    = (const float*)d_in[0];
    const float* rw   = (const float*)d_in[1];
    const float* bias = (const float*)d_in[2];
    const float* w1   = (const float*)d_in[3];
    const float* w3   = (const float*)d_in[4];
    const float* w2   = (const float*)d_in[5];
    const float* sw1  = (const float*)d_in[6];
    const float* sw3  = (const float*)d_in[7];
    const float* sw2  = (const float*)d_in[8];
    float* out = (float*)d_out;

    cudaFuncSetAttribute(gemm1_kernel, cudaFuncAttributeMaxDynamicSharedMemorySize, SMEM1_BYTES);
    cudaFuncSetAttribute(gemm2_kernel, cudaFuncAttributeMaxDynamicSharedMemorySize, SMEM2_BYTES);

    __half* w1h;  cudaGetSymbolAddress((void**)&w1h, g_w1h);
    __half* w3h;  cudaGetSymbolAddress((void**)&w3h, g_w3h);
    __half* w2h;  cudaGetSymbolAddress((void**)&w2h, g_w2h);
    __half* s1h;  cudaGetSymbolAddress((void**)&s1h, g_sw1h);
    __half* s3h;  cudaGetSymbolAddress((void**)&s3h, g_sw3h);
    __half* s2h;  cudaGetSymbolAddress((void**)&s2h, g_sw2h);

    // counter reset must precede router atomics (cross-kernel ordering)
    reset_counts_kernel<<<1, 32>>>();

    // fused prep: router + out-zero + w1/w3 transposes
    prep_kernel<<<PREP_F1, 256>>>(x, rw, bias, w1, w3, sw1, sw3,
                                  w1h, w3h, s1h, s3h, (float4*)out);

    // gemm1 + overlapped w2/sw2 transpose
    gemm1_kernel<<<2 * G1_BLOCKS, 256, SMEM1_BYTES>>>(w2, sw2, w2h, s2h);

    dim3 grid2(TT / 128, DD / 128, EE + 1);      // (64, 8, 9)
    gemm2_kernel<<<grid2, 256, SMEM2_BYTES>>>(out);
}